// round 8
// baseline (speedup 1.0000x reference)
#include <cuda_runtime.h>

typedef unsigned long long ull;

#define MAXB 4096

static __device__ float g_pos[MAXB];
static __device__ float g_part[32 * MAXB];   // [col-tile][row] partial row sums
static __device__ unsigned g_done = 0;

__device__ __forceinline__ void fma2(ull& d, ull a, ull b) {
    asm("fma.rn.f32x2 %0, %1, %2, %0;" : "+l"(d) : "l"(a), "l"(b));
}

__device__ __forceinline__ float ex2f(float x) {
    float r;
    asm("ex2.approx.f32 %0, %1;" : "=f"(r) : "f"(x));
    return r;
}
__device__ __forceinline__ float lg2f(float x) {
    float r;
    asm("lg2.approx.f32 %0, %1;" : "=f"(r) : "f"(x));
    return r;
}

#define N_AD (64 * 64 * 4)   // A dup: [row][kpair] float4 -> 64 KB (in floats)
#define N_B  (128 * 128)     // B: [k][128 cols] float, col-quad swizzle -> 64 KB

// ---------------- Fused kernel ----------------
// Tile 64 rows x 128 cols, 256 threads = 8 warps, grid (B/128, B/64) = 128 CTAs.
// Warp w: rows w*8..w*8+7. Lane l: cols 4l..4l+3.
// Thread micro-tile: 8 rows x 4 cols; accumulators pack COLUMN pairs.
// A smem (dup): Ad[row][kp] = float4 {a(2kp,r), a(2kp,r), a(2kp+1,r), a(2kp+1,r)}
//   -> broadcast LDS.128 gives two packed dup operands, no register movs.
// B smem: [k][128] floats, col swizzle c ^ (((k>>2)&7)<<2) (quads intact)
//   -> LDS.128 gives float4 = two natural column pairs, no movs.
__global__ void __launch_bounds__(256, 1)
hyp_pair(const float* __restrict__ z, const float* __restrict__ zp,
         float* __restrict__ out, int B) {
    extern __shared__ float smem_f[];
    float* Ad  = smem_f;                      // 64 KB
    float* Bs  = smem_f + N_AD;               // 64 KB
    float* sx2 = Bs + N_B;                    // 64
    float* sy2 = sx2 + 64;                    // 128
    float* syi = sy2 + 128;                   // 128
    unsigned* s_rank = (unsigned*)(syi + 128);
    float*    red    = (float*)(s_rank + 8);  // 8 floats

    const int tid  = threadIdx.x;
    const int lane = tid & 31;
    const int warp = tid >> 5;
    const int row0 = blockIdx.y * 64;
    const int col0 = blockIdx.x * 128;

    // ---- fill A (dup layout [row][kp], coalesced LDG, fused row-norm) ----
    {
        const float4* zA = (const float4*)z + row0 * 32;
        #pragma unroll
        for (int p = 0; p < 8; p++) {
            int r = p * 8 + warp;             // warp owns one full row; lanes sweep k-quads
            float4 v = zA[r * 32 + lane];
            float4* dst = (float4*)Ad + r * 64 + 2 * lane;   // kp = 2*lane, 2*lane+1
            dst[0] = make_float4(v.x, v.x, v.y, v.y);
            dst[1] = make_float4(v.z, v.z, v.w, v.w);
            float s = v.x * v.x + v.y * v.y + v.z * v.z + v.w * v.w;
            #pragma unroll
            for (int o = 16; o; o >>= 1) s += __shfl_xor_sync(0xffffffffu, s, o);
            if (lane == 0) sx2[r] = s;
        }
    }
    // ---- fill B (swizzled transpose, fused col-norm) ----
    {
        const float4* zB = (const float4*)zp + col0 * 32;
        #pragma unroll
        for (int p = 0; p < 16; p++) {
            int cj = p * 8 + warp;
            float4 v = zB[cj * 32 + lane];
            int sswz = (lane & 7) << 2;       // kq = lane -> swz = ((k>>2)&7)<<2
            Bs[(lane * 4 + 0) * 128 + (cj ^ sswz)] = v.x;
            Bs[(lane * 4 + 1) * 128 + (cj ^ sswz)] = v.y;
            Bs[(lane * 4 + 2) * 128 + (cj ^ sswz)] = v.z;
            Bs[(lane * 4 + 3) * 128 + (cj ^ sswz)] = v.w;
            float s = v.x * v.x + v.y * v.y + v.z * v.z + v.w * v.w;
            #pragma unroll
            for (int o = 16; o; o >>= 1) s += __shfl_xor_sync(0xffffffffu, s, o);
            if (lane == 0) {
                sy2[cj] = s;
                syi[cj] = rsqrtf(fmaxf(s, 1e-24f));   // == 1/max(norm,1e-12)
            }
        }
    }
    __syncthreads();

    ull acc[8][2];                            // [row][col-pair]
    #pragma unroll
    for (int i = 0; i < 8; i++) { acc[i][0] = 0ull; acc[i][1] = 0ull; }

    const int rb   = warp * 8;
    const int bcol = lane * 4;
    const ull* AdU = (const ull*)Ad;          // [row*128 + kp*2 + {0,1}]

    #pragma unroll 4
    for (int kp = 0; kp < 64; kp++) {
        const int k0 = 2 * kp;
        const int s0 = ((k0 >> 2) & 7) << 2;
        const int s1 = (((k0 + 1) >> 2) & 7) << 2;
        // B: two natural column pairs per k
        ull b00, b01, b10, b11;
        {
            const float4 bv0 = *(const float4*)(Bs + k0 * 128 + (bcol ^ s0));
            const float4 bv1 = *(const float4*)(Bs + (k0 + 1) * 128 + (bcol ^ s1));
            b00 = ((const ull*)&bv0)[0]; b01 = ((const ull*)&bv0)[1];
            b10 = ((const ull*)&bv1)[0]; b11 = ((const ull*)&bv1)[1];
        }
        #pragma unroll
        for (int i = 0; i < 8; i++) {
            // broadcast LDS.128: {dup a(k0,r), dup a(k0+1,r)}
            const ull* ap = AdU + (rb + i) * 128 + kp * 2;
            ull a0 = ap[0];
            ull a1 = ap[1];
            fma2(acc[i][0], a0, b00); fma2(acc[i][1], a0, b01);
            fma2(acc[i][0], a1, b10); fma2(acc[i][1], a1, b11);
        }
    }

    // ---- epilogue: thread owns rows rb..rb+7, cols col0 + 4*lane..+3 ----
    {
        float y2v[4], yiv[4];
        #pragma unroll
        for (int c = 0; c < 4; c++) {
            y2v[c] = sy2[bcol + c];
            yiv[c] = syi[bcol + c];
        }
        const float Cc = 0.05f;
        const float SQC = 0.22360679775f;     // sqrt(c)
        #pragma unroll
        for (int i = 0; i < 8; i++) {
            float dv[4];
            #pragma unroll
            for (int cp = 0; cp < 2; cp++) {
                unsigned lo, hi;
                asm("mov.b64 {%0, %1}, %2;" : "=r"(lo), "=r"(hi) : "l"(acc[i][cp]));
                dv[2 * cp + 0] = __uint_as_float(lo);
                dv[2 * cp + 1] = __uint_as_float(hi);
            }
            int li = rb + i;
            int gi = row0 + li;
            float x2  = sx2[li];
            float xin = rsqrtf(fmaxf(x2, 1e-24f));
            float B1 = 1.0f - Cc * x2;
            float s = 0.0f;
            #pragma unroll
            for (int c = 0; c < 4; c++) {
                int gj = col0 + bcol + c;
                float d  = dv[c];                     // <z_i, z'_j>
                float y2 = y2v[c];
                float A1  = 1.0f + Cc * (y2 - 2.0f * d);
                float den = fmaxf(1.0f - 2.0f * Cc * d + Cc * Cc * x2 * y2, 1e-6f);
                float num = fmaxf(A1 * A1 * x2 - 2.0f * A1 * B1 * d + B1 * B1 * y2, 0.0f);
                float mn  = num * rsqrtf(fmaxf(num, 1e-37f));   // sqrt(num)
                float t   = SQC * mn;
                float pn  = den + t;
                float qn  = fmaxf(den - t, 1e-6f * den);        // u <= 1-1e-6 guard
                float l2  = lg2f(pn) - lg2f(qn);                // log2((1+u)/(1-u))
                float cosv = d * xin * yiv[c];
                if (gi == gj) {
                    g_pos[gi] = 5.0f * cosv - 15.4993876f * l2; // 22.3607*ln2
                } else {
                    s += ex2f(7.21347520f * cosv - 22.3606798f * l2);
                }
            }
            #pragma unroll
            for (int o = 16; o; o >>= 1) s += __shfl_xor_sync(0xffffffffu, s, o);
            if (lane == 0) g_part[blockIdx.x * MAXB + gi] = s;
        }
    }

    // ---- last CTA performs the final reduction (deterministic) ----
    __syncthreads();
    __threadfence();
    if (tid == 0) *s_rank = atomicAdd(&g_done, 1u);
    __syncthreads();
    unsigned nblk = gridDim.x * gridDim.y;
    if (*s_rank == nblk - 1) {
        int nparts = gridDim.x;
        float s = 0.0f;
        for (int i = tid; i < B; i += 256) {
            float dsum = 0.0f;
            #pragma unroll
            for (int p = 0; p < 8; p++) dsum += g_part[p * MAXB + i];
            s += __logf(dsum) - g_pos[i];
        }
        #pragma unroll
        for (int o = 16; o; o >>= 1) s += __shfl_xor_sync(0xffffffffu, s, o);
        if (lane == 0) red[warp] = s;
        __syncthreads();
        if (tid == 0) {
            float tot = 0.0f;
            #pragma unroll
            for (int w = 0; w < 8; w++) tot += red[w];
            out[0] = tot / (float)B;
            g_done = 0;                         // reset for next graph replay
        }
    }
}

extern "C" void kernel_launch(void* const* d_in, const int* in_sizes, int n_in,
                              void* d_out, int out_size) {
    (void)n_in; (void)out_size;
    const float* z  = (const float*)d_in[0];
    const float* zp = (const float*)d_in[1];
    int B = in_sizes[0] / 128;

    int smem = (N_AD + N_B) * (int)sizeof(float) + 384 * (int)sizeof(float); // ~129.5 KB
    cudaFuncSetAttribute(hyp_pair, cudaFuncAttributeMaxDynamicSharedMemorySize, smem);
    dim3 grid(B / 128, B / 64);
    hyp_pair<<<grid, 256, smem>>>(z, zp, (float*)d_out, B);
}